// round 11
// baseline (speedup 1.0000x reference)
#include <cuda_runtime.h>
#include <cuda_bf16.h>
#include <cstdint>

#define N_IN       16
#define FANIN      16
#define N_NODES    512
#define N_OUT      64
#define BATCH      32768
#define HALF       (BATCH / 2)          // 16384
#define OUT_START  (N_NODES - N_OUT)    // node 448

#define THREADS    128
#define GRID       (HALF / THREADS)     // 128 CTAs, 4 warps/SM = 1/SMSP

#define PAD_NODES  (N_NODES + 2)        // 2 zero rows for lookahead tail

__device__ __forceinline__ float tanh_approx(float x) {
    float y; asm("tanh.approx.f32 %0, %1;" : "=f"(y) : "f"(x)); return y;
}

// Shared memory (float units)
#define SMEM_W   0
#define SMEM_B   (PAD_NODES * FANIN)
#define SMEM_R   (SMEM_B + PAD_NODES)
#define SMEM_F32 (SMEM_R + N_OUT)

__global__ void __launch_bounds__(THREADS, 1)
neat_forward_la2(const float* __restrict__ x,
                 const float* __restrict__ w,      // [512][16]
                 const float* __restrict__ bias,   // [512]
                 const float* __restrict__ resp,   // [512]
                 float*       __restrict__ out)    // [BATCH][64]
{
    extern __shared__ __align__(16) float sh[];
    const int tid = threadIdx.x;

    // Fold source responses into consumer weights: w'[i][t] = w[i][t]*resp[i+t-16]
    // (identity for input sources). Window carries RAW tanh values.
    for (int i = tid; i < N_NODES * FANIN; i += THREADS) {
        const int node = i >> 4, t = i & 15;
        const int g = node + t;
        const float s = (g >= N_IN) ? resp[g - N_IN] : 1.0f;
        sh[SMEM_W + i] = w[i] * s;
    }
    for (int i = tid; i < 2 * FANIN; i += THREADS) sh[SMEM_W + N_NODES * FANIN + i] = 0.0f;
    for (int i = tid; i < N_NODES; i += THREADS) sh[SMEM_B + i] = bias[i];
    if (tid < 2) sh[SMEM_B + N_NODES + tid] = 0.0f;
    for (int i = tid; i < N_OUT; i += THREADS) sh[SMEM_R + i] = resp[OUT_START + i];
    __syncthreads();

    // Two chains per thread share one weight-load stream.
    const int b0 = blockIdx.x * THREADS + tid;
    const int b1 = b0 + HALF;

    // Circular windows: slot (n+m)&15 holds global n+m (m = 1..16) at node n's end.
    float vA[16], vB[16];
    {
        const float4* x0 = (const float4*)(x + (size_t)b0 * N_IN);
        const float4* x1 = (const float4*)(x + (size_t)b1 * N_IN);
        #pragma unroll
        for (int q = 0; q < 4; q++) {
            float4 t0 = x0[q], t1 = x1[q];
            vA[4*q+0] = t0.x; vA[4*q+1] = t0.y; vA[4*q+2] = t0.z; vA[4*q+3] = t0.w;
            vB[4*q+0] = t1.x; vB[4*q+1] = t1.y; vB[4*q+2] = t1.z; vB[4*q+3] = t1.w;
        }
    }

    float* outp0 = out + (size_t)b0 * N_OUT;
    float* outp1 = out + (size_t)b1 * N_OUT;

    // ---- Pipeline prologue ----
    // ppc : partial of node n   with taps 0..14 (+bias) folded; w15c = w'[n][15]
    // ppn : partial of node n+1 with taps 0..13 (+bias) folded; w14n/w15n saved
    float w0r[16], w1r[16];
    #pragma unroll
    for (int t = 0; t < 16; t++) { w0r[t] = sh[SMEM_W + t]; w1r[t] = sh[SMEM_W + 16 + t]; }

    float ppAc = sh[SMEM_B + 0], ppBc = ppAc;
    #pragma unroll
    for (int t = 0; t < 15; t++) {        // node 0 taps 0..14 = inputs 0..14
        ppAc = fmaf(vA[t], w0r[t], ppAc);
        ppBc = fmaf(vB[t], w0r[t], ppBc);
    }
    float w15c = w0r[15];

    float ppAn = sh[SMEM_B + 1], ppBn = ppAn;
    #pragma unroll
    for (int t = 0; t < 14; t++) {        // node 1 taps 0..13 = inputs 1..14
        ppAn = fmaf(vA[1 + t], w1r[t], ppAn);
        ppBn = fmaf(vB[1 + t], w1r[t], ppBn);
    }
    float w14n = w1r[14], w15n = w1r[15];

    #pragma unroll 1
    for (int g = 0; g < N_NODES / 16; g++) {
        #pragma unroll
        for (int j = 0; j < 16; j++) {
            const int node = g * 16 + j;

            // ---- SERIAL PATH (only thing that depends on node-1): fma + tanh
            const float ylA = vA[(j + 15) & 15];   // global node+15 = y_{node-1}
            const float ylB = vB[(j + 15) & 15];
            const float yA = tanh_approx(fmaf(ylA, w15c, ppAc));
            const float yB = tanh_approx(fmaf(ylB, w15c, ppBc));
            vA[j] = yA;
            vB[j] = yB;

            if (g >= OUT_START / 16) {
                const int o = node - OUT_START;
                const float r = sh[SMEM_R + o];
                outp0[o] = yA * r;
                outp1[o] = yB * r;
            }

            // ---- OFF-PATH WORK (fills the tanh shadow) ----
            // fold tap14 of node+1: global node+15 (same value as ylA/ylB)
            ppAn = fmaf(ylA, w14n, ppAn);
            ppBn = fmaf(ylB, w14n, ppBn);

            // load row node+2 and compute its 14-tap partial
            // (taps 0..13 -> globals node+2 .. node+15, all in the window)
            const float4* wv = (const float4*)(sh + SMEM_W + (node + 2) * FANIN);
            const float4 q0 = wv[0], q1 = wv[1], q2 = wv[2], q3 = wv[3];
            const float  bb = sh[SMEM_B + node + 2];

            float pA0 = fmaf(vA[(j + 2)  & 15], q0.x, bb);
            float pA1 =      vA[(j + 3)  & 15] * q0.y;
            float pA2 =      vA[(j + 4)  & 15] * q0.z;
            float pA3 =      vA[(j + 5)  & 15] * q0.w;
            float pB0 = fmaf(vB[(j + 2)  & 15], q0.x, bb);
            float pB1 =      vB[(j + 3)  & 15] * q0.y;
            float pB2 =      vB[(j + 4)  & 15] * q0.z;
            float pB3 =      vB[(j + 5)  & 15] * q0.w;

            pA0 = fmaf(vA[(j + 6)  & 15], q1.x, pA0);
            pA1 = fmaf(vA[(j + 7)  & 15], q1.y, pA1);
            pA2 = fmaf(vA[(j + 8)  & 15], q1.z, pA2);
            pA3 = fmaf(vA[(j + 9)  & 15], q1.w, pA3);
            pB0 = fmaf(vB[(j + 6)  & 15], q1.x, pB0);
            pB1 = fmaf(vB[(j + 7)  & 15], q1.y, pB1);
            pB2 = fmaf(vB[(j + 8)  & 15], q1.z, pB2);
            pB3 = fmaf(vB[(j + 9)  & 15], q1.w, pB3);

            pA0 = fmaf(vA[(j + 10) & 15], q2.x, pA0);
            pA1 = fmaf(vA[(j + 11) & 15], q2.y, pA1);
            pA2 = fmaf(vA[(j + 12) & 15], q2.z, pA2);
            pA3 = fmaf(vA[(j + 13) & 15], q2.w, pA3);
            pB0 = fmaf(vB[(j + 10) & 15], q2.x, pB0);
            pB1 = fmaf(vB[(j + 11) & 15], q2.y, pB1);
            pB2 = fmaf(vB[(j + 12) & 15], q2.z, pB2);
            pB3 = fmaf(vB[(j + 13) & 15], q2.w, pB3);

            pA0 = fmaf(vA[(j + 14) & 15], q3.x, pA0);   // tap 12
            pA1 = fmaf(ylA,               q3.y, pA1);   // tap 13 = global node+15
            pB0 = fmaf(vB[(j + 14) & 15], q3.x, pB0);
            pB1 = fmaf(ylB,               q3.y, pB1);

            const float PA = (pA0 + pA1) + (pA2 + pA3);
            const float PB = (pB0 + pB1) + (pB2 + pB3);

            // ---- rotate pipeline state ----
            ppAc = ppAn; ppBc = ppBn; w15c = w15n;
            ppAn = PA;   ppBn = PB;   w14n = q3.z; w15n = q3.w;
        }
    }
}

extern "C" void kernel_launch(void* const* d_in, const int* in_sizes, int n_in,
                              void* d_out, int out_size) {
    const float* x    = (const float*)d_in[0];   // [BATCH, 16]
    const float* w    = (const float*)d_in[1];   // [512, 16]
    const float* bias = (const float*)d_in[2];   // [512]
    const float* resp = (const float*)d_in[3];   // [512]
    // d_in[4] (src_idx) is the fixed sliding-window topology; baked into indexing.
    float* out = (float*)d_out;                  // [BATCH, 64]

    const int smem_bytes = SMEM_F32 * (int)sizeof(float);   // ~35 KB
    neat_forward_la2<<<GRID, THREADS, smem_bytes>>>(x, w, bias, resp, out);
}

// round 12
// speedup vs baseline: 1.1383x; 1.1383x over previous
#include <cuda_runtime.h>
#include <cuda_bf16.h>
#include <cstdint>

#define N_IN       16
#define FANIN      16
#define N_NODES    512
#define N_OUT      64
#define BATCH      32768
#define OUT_START  (N_NODES - N_OUT)    // node 448

#define THREADS    256
#define GRID       (BATCH / THREADS)    // 128 CTAs, 8 warps/SM = 2/SMSP

#define PAD_NODES  (N_NODES + 2)        // rows 512,513 zero (lookahead tail)

using u32 = unsigned int;

__constant__ float cB[PAD_NODES] = {};  // bias (zero-padded), via const port
__constant__ float cR[N_OUT]     = {};  // response of output nodes

__device__ __forceinline__ float tanh_approx(float x) {
    float y; asm("tanh.approx.f32 %0, %1;" : "=f"(y) : "f"(x)); return y;
}
__device__ __forceinline__ u32 smem_u32(const void* p) {
    u32 a;
    asm("{ .reg .u64 t; cvta.to.shared.u64 t, %1; cvt.u32.u64 %0, t; }"
        : "=r"(a) : "l"(p));
    return a;
}
// volatile: the row prefetch must not be sunk to its consumer (next iteration)
__device__ __forceinline__ void lds_v4(float4& d, u32 addr) {
    asm volatile("ld.shared.v4.f32 {%0,%1,%2,%3}, [%4];"
                 : "=f"(d.x), "=f"(d.y), "=f"(d.z), "=f"(d.w) : "r"(addr));
}

__global__ void __launch_bounds__(THREADS, 1)
neat_forward_rowpipe(const float* __restrict__ x,
                     const float* __restrict__ w,      // [512][16]
                     const float* __restrict__ resp,   // [512]
                     float*       __restrict__ out)    // [BATCH][64]
{
    __shared__ __align__(16) float sh_w[PAD_NODES * FANIN];   // ~32.9 KB

    const int tid = threadIdx.x;

    // Fold source responses into consumer weights:
    //   w'[i][t] = w[i][t] * resp[i + t - 16]  (identity for input sources).
    // Window carries RAW tanh values; resp applied only at output stores.
    for (int i = tid; i < N_NODES * FANIN; i += THREADS) {
        const int node = i >> 4, t = i & 15;
        const int g = node + t;
        const float s = (g >= N_IN) ? resp[g - N_IN] : 1.0f;
        sh_w[i] = w[i] * s;
    }
    for (int i = tid; i < 2 * FANIN; i += THREADS)
        sh_w[N_NODES * FANIN + i] = 0.0f;                      // pad rows
    __syncthreads();

    const int b = blockIdx.x * THREADS + tid;   // one batch element per thread

    // Circular window: v[g & 15] = value at global index g.
    float v[16];
    {
        const float4* xv = (const float4*)(x + (size_t)b * N_IN);
        #pragma unroll
        for (int q = 0; q < 4; q++) {
            float4 t = xv[q];
            v[4*q+0] = t.x; v[4*q+1] = t.y; v[4*q+2] = t.z; v[4*q+3] = t.w;
        }
    }

    float* outp = out + (size_t)b * N_OUT;
    const u32 wbase = smem_u32(sh_w);           // row stride 64 B

    // ---- Pipeline prologue ----
    // pp   : partial of node 0 (taps 0..14 + bias), w15c = w'[0][15]
    // cq*  : weight row of node 1 (consumed next iteration)
    float pp, w15c;
    {
        const float* r0 = sh_w;                 // row 0
        float a0 = fmaf(v[0], r0[0], cB[0]);
        float a1 =      v[1] * r0[1];
        #pragma unroll
        for (int t = 2; t < 15; t += 2) {
            a0 = fmaf(v[t],     r0[t],     a0);
            a1 = fmaf(v[t + 1], r0[t + 1], a1);
        }
        // loop above covers t=2..13 (+t=14 below, since 15 taps total: 0..14)
        a0 = fmaf(v[14], r0[14], a0);
        pp = a0 + a1;
        w15c = r0[15];
    }
    float4 cq0, cq1, cq2, cq3;                  // row of node 1
    {
        const float4* r1 = (const float4*)(sh_w + FANIN);
        cq0 = r1[0]; cq1 = r1[1]; cq2 = r1[2]; cq3 = r1[3];
    }

    float4 ob;                                  // output staging (float4 stores)

    #pragma unroll 1
    for (int g = 0; g < N_NODES / 16; g++) {
        #pragma unroll
        for (int j = 0; j < 16; j++) {
            const int node = g * 16 + j;

            // ---- A: serial path (only dependence on node-1): fma + tanh ----
            const float yl  = v[(j + 15) & 15];         // y_{node-1}
            const float agg = fmaf(yl, w15c, pp);
            const float y   = tanh_approx(agg);
            v[j] = y;

            if (node >= OUT_START) {
                const int o = node - OUT_START;
                const float yo = y * cR[o];
                if ((j & 3) == 0) ob.x = yo;
                if ((j & 3) == 1) ob.y = yo;
                if ((j & 3) == 2) ob.z = yo;
                if ((j & 3) == 3) { ob.w = yo;
                    *(float4*)(outp + (o - 3)) = ob; }
            }

            // ---- B: prefetch weight row node+2 (volatile, consumed at j+1) --
            float4 nq0, nq1, nq2, nq3;
            const u32 ra = wbase + (u32)(node + 2) * 64;
            lds_v4(nq0, ra);
            lds_v4(nq1, ra + 16);
            lds_v4(nq2, ra + 32);
            lds_v4(nq3, ra + 48);

            // ---- C: partial for node+1 from row loaded LAST iteration ------
            // taps t=0..14 -> globals node+1 .. node+15 (excludes y_node!),
            // i.e. window slots (j+1)..(j+15): fully off the serial path.
            float b0 = fmaf(v[(j + 1)  & 15], cq0.x, cB[node + 1]);
            float b1 =      v[(j + 2)  & 15] * cq0.y;
            b0 = fmaf(v[(j + 3)  & 15], cq0.z, b0);
            b1 = fmaf(v[(j + 4)  & 15], cq0.w, b1);
            b0 = fmaf(v[(j + 5)  & 15], cq1.x, b0);
            b1 = fmaf(v[(j + 6)  & 15], cq1.y, b1);
            b0 = fmaf(v[(j + 7)  & 15], cq1.z, b0);
            b1 = fmaf(v[(j + 8)  & 15], cq1.w, b1);
            b0 = fmaf(v[(j + 9)  & 15], cq2.x, b0);
            b1 = fmaf(v[(j + 10) & 15], cq2.y, b1);
            b0 = fmaf(v[(j + 11) & 15], cq2.z, b0);
            b1 = fmaf(v[(j + 12) & 15], cq2.w, b1);
            b0 = fmaf(v[(j + 13) & 15], cq3.x, b0);
            b1 = fmaf(v[(j + 14) & 15], cq3.y, b1);
            b0 = fmaf(v[(j + 15) & 15], cq3.z, b0);     // t=14 (y_{node-1})
            pp   = b0 + b1;
            w15c = cq3.w;

            // ---- rotate row pipeline ----
            cq0 = nq0; cq1 = nq1; cq2 = nq2; cq3 = nq3;
        }
    }
}

extern "C" void kernel_launch(void* const* d_in, const int* in_sizes, int n_in,
                              void* d_out, int out_size) {
    const float* x    = (const float*)d_in[0];   // [BATCH, 16]
    const float* w    = (const float*)d_in[1];   // [512, 16]
    const float* bias = (const float*)d_in[2];   // [512]
    const float* resp = (const float*)d_in[3];   // [512]
    // d_in[4] (src_idx) is the fixed sliding-window topology; baked into indexing.
    float* out = (float*)d_out;                  // [BATCH, 64]

    cudaMemcpyToSymbolAsync(cB, bias, N_NODES * sizeof(float), 0,
                            cudaMemcpyDeviceToDevice, 0);
    cudaMemcpyToSymbolAsync(cR, resp + OUT_START, N_OUT * sizeof(float), 0,
                            cudaMemcpyDeviceToDevice, 0);

    neat_forward_rowpipe<<<GRID, THREADS>>>(x, w, resp, out);
}